// round 8
// baseline (speedup 1.0000x reference)
#include <cuda_runtime.h>
#include <cuda_fp16.h>
#include <math.h>

// Problem constants
#define BB 2
#define SS 2048
#define HID 2048
#define NH 16
#define NKVH 2
#define DH 256
#define ROT 64
#define MM (BB*SS)          // 4096 tokens
#define QGN (NH*DH*2)       // 8192
#define KVN (NKVH*DH)       // 512
#define ODIM (NH*DH)        // 4096

// Scratch (device globals). GEMM A/B operands live in PANELIZED layouts:
//  A-panels: 256 rows x 64 halfs per block (32KB), rows of 128B, SW128 xor.
//  B-panels: 128 rows x 64 halfs per block (16KB).
__device__ __half g_hs  [(size_t)MM * HID];          // panelized A (nkb=32)
__device__ __half g_wqt [(size_t)QGN * HID];         // panelized B (nkb=32)
__device__ __half g_wkvt[(size_t)(2*KVN) * HID];     // panelized B (nkb=32)
__device__ __half g_wot [(size_t)HID * ODIM];        // panelized B (nkb=64)
__device__ float  g_qg  [(size_t)MM * QGN];          // row-major fp32
__device__ float  g_kv  [(size_t)MM * 2*KVN];        // row-major fp32
__device__ __half g_q   [(size_t)BB * NH  * SS * DH];   // [b][h][s][d], scale folded
__device__ __half g_kr  [(size_t)BB * NKVH * SS * DH];  // [b][kvh][s][d]
__device__ __half g_vr  [(size_t)BB * NKVH * DH * SS];  // [b][kvh][d][s] (TRANSPOSED)
__device__ __half g_attn[(size_t)MM * ODIM];            // panelized A (nkb=64)

// ---------------- device helpers ----------------
__device__ __forceinline__ unsigned smem_u32(const void* p) {
    unsigned a;
    asm("{ .reg .u64 t; cvta.to.shared.u64 t, %1; cvt.u32.u64 %0, t; }" : "=r"(a) : "l"(p));
    return a;
}
__device__ __forceinline__ void mma_f16(float c[4], const unsigned a[4], const unsigned* b) {
    asm volatile(
        "mma.sync.aligned.m16n8k16.row.col.f32.f16.f16.f32 "
        "{%0,%1,%2,%3}, {%4,%5,%6,%7}, {%8,%9}, {%0,%1,%2,%3};\n"
        : "+f"(c[0]), "+f"(c[1]), "+f"(c[2]), "+f"(c[3])
        : "r"(a[0]), "r"(a[1]), "r"(a[2]), "r"(a[3]), "r"(b[0]), "r"(b[1]));
}
__device__ __forceinline__ void ldsm4(unsigned r[4], const void* p) {
    unsigned a = smem_u32(p);
    asm volatile("ldmatrix.sync.aligned.m8n8.x4.shared.b16 {%0,%1,%2,%3}, [%4];\n"
                 : "=r"(r[0]), "=r"(r[1]), "=r"(r[2]), "=r"(r[3]) : "r"(a));
}
__device__ __forceinline__ void mbar_init(unsigned mbar, unsigned cnt) {
    asm volatile("mbarrier.init.shared.b64 [%0], %1;" :: "r"(mbar), "r"(cnt) : "memory");
}
__device__ __forceinline__ void mbar_expect_tx(unsigned mbar, unsigned bytes) {
    asm volatile("mbarrier.arrive.expect_tx.shared.b64 _, [%0], %1;" :: "r"(mbar), "r"(bytes) : "memory");
}
__device__ __forceinline__ void mbar_wait(unsigned mbar, unsigned parity) {
    asm volatile(
        "{\n\t.reg .pred P;\n\t"
        "WL_%=:\n\t"
        "mbarrier.try_wait.parity.acquire.cta.shared::cta.b64 P, [%0], %1, 0x989680;\n\t"
        "@P bra.uni WD_%=;\n\t"
        "bra.uni WL_%=;\n\t"
        "WD_%=:\n\t}"
        :: "r"(mbar), "r"(parity) : "memory");
}
// 1D bulk copy gmem -> smem (sm_90 base feature; SASS UBLKCP)
__device__ __forceinline__ void bulk_g2s(unsigned dst, const void* src, unsigned bytes, unsigned mbar) {
    asm volatile(
        "cp.async.bulk.shared::cluster.global.mbarrier::complete_tx::bytes [%0], [%1], %2, [%3];"
        :: "r"(dst), "l"(src), "r"(bytes), "r"(mbar) : "memory");
}

// Panel offsets (bytes). A: 256-row panels; B: 128-row panels. 64-half k-blocks.
__device__ __forceinline__ size_t panA(int m, int k, int nkb) {
    return ((size_t)((m >> 8) * nkb + (k >> 6)) << 15) + (size_t)((m & 255) * 128)
         + (size_t)(((k & 63) * 2) ^ ((m & 7) << 4));
}
__device__ __forceinline__ size_t panB(int n, int k, int nkb) {
    return ((size_t)((n >> 7) * nkb + (k >> 6)) << 14) + (size_t)((n & 127) * 128)
         + (size_t)(((k & 63) * 2) ^ ((n & 7) << 4));
}

// ---------------------------------------------------------------------------
// Prep: hs fp32 row-major -> panelized fp16 A (nkb = HID/64 = 32)
// ---------------------------------------------------------------------------
__global__ __launch_bounds__(256) void pack_hs_kernel(const float* __restrict__ src,
                                                      __half* __restrict__ dst)
{
    const int n8 = MM * HID / 8;
    for (int idx = blockIdx.x * 256 + threadIdx.x; idx < n8; idx += gridDim.x * 256) {
        const int m = idx >> 8;             // HID/8 = 256 chunks per row
        const int k = (idx & 255) * 8;
        float4 v0 = ((const float4*)src)[idx * 2];
        float4 v1 = ((const float4*)src)[idx * 2 + 1];
        __half2 h[4];
        h[0] = __floats2half2_rn(v0.x, v0.y);
        h[1] = __floats2half2_rn(v0.z, v0.w);
        h[2] = __floats2half2_rn(v1.x, v1.y);
        h[3] = __floats2half2_rn(v1.z, v1.w);
        *(uint4*)((char*)dst + panA(m, k, 32)) = *(uint4*)h;
    }
}

// ---------------------------------------------------------------------------
// Prep: weight [K][N] fp32 -> panelized fp16 B (transpose), n offset by noff.
// ---------------------------------------------------------------------------
__global__ __launch_bounds__(256) void pack_w_kernel(
    const float* __restrict__ src, __half* __restrict__ dst, int Kd, int Nd,
    int nkb, int noff)
{
    __shared__ float t[32][33];
    const int x = blockIdx.x * 32 + threadIdx.x;       // n in src
    const int y0 = blockIdx.y * 32;                    // k in src
#pragma unroll
    for (int i = 0; i < 32; i += 8)
        t[threadIdx.y + i][threadIdx.x] = src[(size_t)(y0 + threadIdx.y + i) * Nd + x];
    __syncthreads();
    const int k = blockIdx.y * 32 + threadIdx.x;
    const int n0 = blockIdx.x * 32;
#pragma unroll
    for (int i = 0; i < 32; i += 8) {
        const int n = n0 + threadIdx.y + i + noff;
        *(__half*)((char*)dst + panB(n, k, nkb)) =
            __float2half(t[threadIdx.x][threadIdx.y + i]);
    }
    (void)Kd;
}

// ---------------------------------------------------------------------------
// fp16 GEMM, bulk-copy pipelined: A panelized [Mpanels][nkb][256x64],
// B panelized [Npanels][nkb][128x64], C [M][N] fp32 row-major.
// CTA tile 256x128, BK=64, 3-stage ring, 8 warps (4x2), warp 64x64.
// ---------------------------------------------------------------------------
#define GK_SMEM (1024 + 3*32768 + 3*16384)

__global__ __launch_bounds__(256, 1) void hgemm_kernel(
    const __half* __restrict__ A, const __half* __restrict__ Bt,
    float* __restrict__ C, int N, int nkb)
{
    extern __shared__ char smem_raw[];
    const unsigned sb = smem_u32(smem_raw);
    char* Abase = smem_raw + 1024;
    char* Bbase = smem_raw + 1024 + 3 * 32768;

    const int tid = threadIdx.x;
    const int lane = tid & 31;
    const int g = lane >> 2, t = lane & 3;
    const int wid = tid >> 5;
    const int m0 = (wid >> 1) * 64;
    const int n0 = (wid & 1) * 64;
    const int bx = blockIdx.x, by = blockIdx.y;

    const int a_row = ((lane >> 3) & 1) * 8 + (lane & 7);
    const int a_kh  = (lane >> 4) * 8;
    const int b_row = ((lane >> 4) & 1) * 8 + (lane & 7);
    const int b_kh  = ((lane >> 3) & 1) * 8;

    if (tid == 0) {
        mbar_init(sb + 0, 1);
        mbar_init(sb + 8, 1);
        mbar_init(sb + 16, 1);
    }
    __syncthreads();

    if (tid == 0) {
#pragma unroll
        for (int s = 0; s < 3; s++) {
            mbar_expect_tx(sb + s * 8, 49152);
            bulk_g2s(sb + 1024 + s * 32768,
                     (const char*)A + ((size_t)(by * nkb + s) << 15), 32768, sb + s * 8);
            bulk_g2s(sb + 1024 + 3 * 32768 + s * 16384,
                     (const char*)Bt + ((size_t)(bx * nkb + s) << 14), 16384, sb + s * 8);
        }
    }

    float acc[4][8][4];
#pragma unroll
    for (int mt = 0; mt < 4; mt++)
#pragma unroll
        for (int nt = 0; nt < 8; nt++)
#pragma unroll
            for (int r = 0; r < 4; r++) acc[mt][nt][r] = 0.f;

    for (int i = 0; i < nkb; i++) {
        const int slot = i % 3;
        const unsigned phase = (unsigned)((i / 3) & 1);
        mbar_wait(sb + slot * 8, phase);
        const char* Ad = Abase + slot * 32768;
        const char* Bd = Bbase + slot * 16384;

#pragma unroll
        for (int kk = 0; kk < 64; kk += 16) {
            unsigned a[4][4], bfr[4][4];
#pragma unroll
            for (int mt = 0; mt < 4; mt++) {
                const int row = m0 + mt * 16 + a_row;
                const int cb = (kk + a_kh) * 2;
                ldsm4(a[mt], Ad + row * 128 + (cb ^ ((row & 7) << 4)));
            }
#pragma unroll
            for (int p = 0; p < 4; p++) {
                const int row = n0 + p * 16 + b_row;
                const int cb = (kk + b_kh) * 2;
                ldsm4(bfr[p], Bd + row * 128 + (cb ^ ((row & 7) << 4)));
            }
#pragma unroll
            for (int mt = 0; mt < 4; mt++)
#pragma unroll
                for (int nt = 0; nt < 8; nt++)
                    mma_f16(acc[mt][nt], a[mt], &bfr[nt >> 1][(nt & 1) * 2]);
        }
        __syncthreads();
        if (tid == 0 && i + 3 < nkb) {
            mbar_expect_tx(sb + slot * 8, 49152);
            bulk_g2s(sb + 1024 + slot * 32768,
                     (const char*)A + ((size_t)(by * nkb + i + 3) << 15), 32768, sb + slot * 8);
            bulk_g2s(sb + 1024 + 3 * 32768 + slot * 16384,
                     (const char*)Bt + ((size_t)(bx * nkb + i + 3) << 14), 16384, sb + slot * 8);
        }
    }

#pragma unroll
    for (int mt = 0; mt < 4; mt++) {
        const int r = by * 256 + m0 + mt * 16 + g;
#pragma unroll
        for (int nt = 0; nt < 8; nt++) {
            const int c = bx * 128 + n0 + nt * 8 + 2 * t;
            *(float2*)(C + (size_t)r * N + c)       = make_float2(acc[mt][nt][0], acc[mt][nt][1]);
            *(float2*)(C + (size_t)(r + 8) * N + c) = make_float2(acc[mt][nt][2], acc[mt][nt][3]);
        }
    }
}

// ---------------------------------------------------------------------------
// Post-process: RMSNorm + RoPE for Q/K, V transpose. fp16 outputs, scale folded.
// ---------------------------------------------------------------------------
__global__ __launch_bounds__(256) void qkv_post_kernel(
    const float* __restrict__ cosp, const float* __restrict__ sinp,
    const float* __restrict__ qw, const float* __restrict__ kw)
{
    const int token = blockIdx.x;
    const int unit  = blockIdx.y;
    const int d     = threadIdx.x;
    const int b = token >> 11;
    const int s = token & 2047;

    __shared__ float sh[DH];
    __shared__ float red[8];

    if (unit < 18) {
        float x;
        const float* w;
        if (unit < 16) {
            x = g_qg[(size_t)token * QGN + unit * 512 + d];
            w = qw;
        } else {
            x = g_kv[(size_t)token * (2*KVN) + (unit - 16) * 256 + d];
            w = kw;
        }
        float v = x * x;
#pragma unroll
        for (int o = 16; o; o >>= 1) v += __shfl_xor_sync(0xffffffffu, v, o);
        if ((d & 31) == 0) red[d >> 5] = v;
        __syncthreads();
        float tot = 0.f;
#pragma unroll
        for (int i = 0; i < 8; i++) tot += red[i];
        float xn = x * rsqrtf(tot * (1.0f / 256.0f) + 1e-6f) * (1.0f + w[d]);
        sh[d] = xn;
        __syncthreads();
        float out = xn;
        if (d < ROT) {
            float rot = (d < 32) ? -sh[d + 32] : sh[d - 32];
            out = xn * cosp[(size_t)token * ROT + d] + rot * sinp[(size_t)token * ROT + d];
        }
        if (unit < 16)
            g_q[(((size_t)b * NH + unit) * SS + s) * DH + d] = __float2half(out * 0.0625f);
        else
            g_kr[(((size_t)b * NKVH + (unit - 16)) * SS + s) * DH + d] = __float2half(out);
    } else {
        const int kvh = unit - 18;
        g_vr[(((size_t)b * NKVH + kvh) * DH + d) * SS + s] =
            __float2half(g_kv[(size_t)token * (2*KVN) + 512 + kvh * 256 + d]);
    }
}

// ---------------------------------------------------------------------------
// Flash attention (fp16 mma m16n8k16 + ldmatrix), round-6 form; epilogue
// writes g_attn in panelized-A layout (nkb=64) for the O-projection.
// ---------------------------------------------------------------------------
#define QS_STR 264
#define KS_STR 264
#define VS_STR 72
#define PS_STR 72
#define FL_SMEM ((128*QS_STR + 64*KS_STR + 256*VS_STR + 128*PS_STR) * 2 + 512 * 4)

__global__ __launch_bounds__(256, 1) void flash_kernel()
{
    extern __shared__ __half smh[];
    __half* Qs = smh;                        // [128][QS_STR]
    __half* Ks = Qs + 128 * QS_STR;          // [64][KS_STR]   (full D=256)
    __half* Vs = Ks + 64 * KS_STR;           // [256][VS_STR]  ([d][key])
    __half* Ps = Vs + 256 * VS_STR;          // [128][PS_STR]
    float* redm = (float*)(Ps + 128 * PS_STR);   // [2][128]
    float* redl = redm + 256;                    // [2][128]

    const int tid = threadIdx.x;
    const int lane = tid & 31;
    const int g = lane >> 2, t = lane & 3;
    const int wid = tid >> 5;
    const int wm = wid >> 1;
    const int wn = wid & 1;

    const int a_row = ((lane >> 3) & 1) * 8 + (lane & 7);
    const int a_kh  = (lane >> 4) * 8;
    const int b_row = ((lane >> 4) & 1) * 8 + (lane & 7);
    const int b_kh  = ((lane >> 3) & 1) * 8;

    const int qt = blockIdx.x;
    const int b  = blockIdx.y >> 4;
    const int h  = blockIdx.y & 15;
    const int kvh = h >> 3;
    const int q0 = qt * 128;

    const __half* Qp  = g_q  + (((size_t)b * NH + h) * SS + q0) * DH;
    const __half* Kp  = g_kr + ((size_t)b * NKVH + kvh) * SS * DH;
    const __half* VpT = g_vr + ((size_t)b * NKVH + kvh) * DH * SS;

#pragma unroll
    for (int it = 0; it < 16; it++) {
        const int idx = tid + it * 256;
        const int r = idx >> 5;
        const int c = (idx & 31) * 8;
        *(uint4*)&Qs[r * QS_STR + c] = *(const uint4*)(Qp + (size_t)r * DH + c);
    }

    float o[2][16][4];
    float mrun[4], lrun[4];
#pragma unroll
    for (int mt = 0; mt < 2; mt++)
#pragma unroll
        for (int cc = 0; cc < 16; cc++)
#pragma unroll
            for (int r = 0; r < 4; r++) o[mt][cc][r] = 0.f;
#pragma unroll
    for (int i = 0; i < 4; i++) { mrun[i] = -1e30f; lrun[i] = 0.f; }

    const int ktmax = 2 * qt + 1;
    for (int kt = 0; kt <= ktmax; kt++) {
        const __half* Kt = Kp + (size_t)(kt * 64) * DH;

        __syncthreads();
#pragma unroll
        for (int it = 0; it < 8; it++) {
            const int idx = tid + it * 256;
            const int key = idx >> 5;
            const int col = (idx & 31) * 8;
            *(uint4*)&Ks[key * KS_STR + col] = *(const uint4*)(Kt + (size_t)key * DH + col);
            const int dl = idx >> 3;
            const int kc = (idx & 7) * 8;
            *(uint4*)&Vs[dl * VS_STR + kc] =
                *(const uint4*)(VpT + (size_t)dl * SS + kt * 64 + kc);
        }
        __syncthreads();

        float s[2][4][4];
#pragma unroll
        for (int mt = 0; mt < 2; mt++)
#pragma unroll
            for (int nt = 0; nt < 4; nt++)
#pragma unroll
                for (int r = 0; r < 4; r++) s[mt][nt][r] = 0.f;

#pragma unroll
        for (int kk = 0; kk < 256; kk += 16) {
            unsigned a[2][4], bq[2][4];
            ldsm4(a[0], Qs + (wm * 32 + a_row)      * QS_STR + kk + a_kh);
            ldsm4(a[1], Qs + (wm * 32 + 16 + a_row) * QS_STR + kk + a_kh);
            ldsm4(bq[0], Ks + (wn * 32 + b_row)      * KS_STR + kk + b_kh);
            ldsm4(bq[1], Ks + (wn * 32 + 16 + b_row) * KS_STR + kk + b_kh);
#pragma unroll
            for (int mt = 0; mt < 2; mt++)
#pragma unroll
                for (int nt = 0; nt < 4; nt++)
                    mma_f16(s[mt][nt], a[mt], &bq[nt >> 1][(nt & 1) * 2]);
        }

        if (kt >= 2 * qt) {
#pragma unroll
            for (int mt = 0; mt < 2; mt++)
#pragma unroll
                for (int nt = 0; nt < 4; nt++)
#pragma unroll
                    for (int r = 0; r < 4; r++) {
                        const int row = q0 + wm * 32 + mt * 16 + (r >> 1) * 8 + g;
                        const int col = kt * 64 + wn * 32 + nt * 8 + 2 * t + (r & 1);
                        if (col > row) s[mt][nt][r] = -1e30f;
                    }
        }

        float al[4];
#pragma unroll
        for (int mt = 0; mt < 2; mt++)
#pragma unroll
            for (int hh = 0; hh < 2; hh++) {
                float v = -1e30f;
#pragma unroll
                for (int nt = 0; nt < 4; nt++)
                    v = fmaxf(v, fmaxf(s[mt][nt][hh * 2], s[mt][nt][hh * 2 + 1]));
                v = fmaxf(v, __shfl_xor_sync(0xffffffffu, v, 1));
                v = fmaxf(v, __shfl_xor_sync(0xffffffffu, v, 2));
                if (t == 0) redm[wn * 128 + wm * 32 + mt * 16 + hh * 8 + g] = v;
            }
        __syncthreads();
#pragma unroll
        for (int mt = 0; mt < 2; mt++)
#pragma unroll
            for (int hh = 0; hh < 2; hh++) {
                const int idx = mt * 2 + hh;
                const int rl = wm * 32 + mt * 16 + hh * 8 + g;
                float tm = fmaxf(redm[rl], redm[128 + rl]);
                float mn = fmaxf(mrun[idx], tm);
                al[idx] = __expf(mrun[idx] - mn);
                mrun[idx] = mn;
                float rs = 0.f;
#pragma unroll
                for (int nt = 0; nt < 4; nt++)
#pragma unroll
                    for (int j = 0; j < 2; j++) {
                        float p = __expf(s[mt][nt][hh * 2 + j] - mn);
                        s[mt][nt][hh * 2 + j] = p;
                        rs += p;
                    }
                rs += __shfl_xor_sync(0xffffffffu, rs, 1);
                rs += __shfl_xor_sync(0xffffffffu, rs, 2);
                if (t == 0) redl[wn * 128 + rl] = rs;
            }
#pragma unroll
        for (int mt = 0; mt < 2; mt++)
#pragma unroll
            for (int nt = 0; nt < 4; nt++) {
                const int r = wm * 32 + mt * 16 + g;
                const int c = wn * 32 + nt * 8 + 2 * t;
                *(__half2*)&Ps[r * PS_STR + c] =
                    __floats2half2_rn(s[mt][nt][0], s[mt][nt][1]);
                *(__half2*)&Ps[(r + 8) * PS_STR + c] =
                    __floats2half2_rn(s[mt][nt][2], s[mt][nt][3]);
            }
        __syncthreads();
#pragma unroll
        for (int mt = 0; mt < 2; mt++)
#pragma unroll
            for (int hh = 0; hh < 2; hh++) {
                const int idx = mt * 2 + hh;
                const int rl = wm * 32 + mt * 16 + hh * 8 + g;
                float ts = redl[rl] + redl[128 + rl];
                lrun[idx] = lrun[idx] * al[idx] + ts;
#pragma unroll
                for (int cc = 0; cc < 16; cc++) {
                    o[mt][cc][hh * 2]     *= al[idx];
                    o[mt][cc][hh * 2 + 1] *= al[idx];
                }
            }

#pragma unroll
        for (int kk = 0; kk < 64; kk += 16) {
            unsigned a[2][4], bv[8][4];
            ldsm4(a[0], Ps + (wm * 32 + a_row)      * PS_STR + kk + a_kh);
            ldsm4(a[1], Ps + (wm * 32 + 16 + a_row) * PS_STR + kk + a_kh);
#pragma unroll
            for (int p = 0; p < 8; p++)
                ldsm4(bv[p], Vs + (wn * 128 + p * 16 + b_row) * VS_STR + kk + b_kh);
#pragma unroll
            for (int mt = 0; mt < 2; mt++)
#pragma unroll
                for (int nt = 0; nt < 16; nt++)
                    mma_f16(o[mt][nt], a[mt], &bv[nt >> 1][(nt & 1) * 2]);
        }
    }

    // epilogue: /l, * sigmoid(gate); write g_attn in panelized-A layout (nkb=64)
#pragma unroll
    for (int mt = 0; mt < 2; mt++)
#pragma unroll
        for (int hh = 0; hh < 2; hh++) {
            const int idx = mt * 2 + hh;
            const int row = q0 + wm * 32 + mt * 16 + hh * 8 + g;
            const int token = b * SS + row;
            const float inv = 1.f / lrun[idx];
#pragma unroll
            for (int cc = 0; cc < 16; cc++) {
                const int col = wn * 128 + cc * 8 + 2 * t;
                const int kd = h * 256 + col;
                float2 gt = *(const float2*)(g_qg + (size_t)token * QGN + h * 512 + 256 + col);
                float ox = o[mt][cc][hh * 2]     * inv / (1.f + __expf(-gt.x));
                float oy = o[mt][cc][hh * 2 + 1] * inv / (1.f + __expf(-gt.y));
                *(__half2*)((char*)g_attn + panA(token, kd, 64)) =
                    __floats2half2_rn(ox, oy);
            }
        }
}

// ---------------------------------------------------------------------------
extern "C" void kernel_launch(void* const* d_in, const int* in_sizes, int n_in,
                              void* d_out, int out_size)
{
    (void)in_sizes; (void)n_in; (void)out_size;
    const float* hs   = (const float*)d_in[0];
    const float* cosp = (const float*)d_in[1];
    const float* sinp = (const float*)d_in[2];
    const float* Wq   = (const float*)d_in[3];
    const float* Wk   = (const float*)d_in[4];
    const float* Wv   = (const float*)d_in[5];
    const float* Wo   = (const float*)d_in[6];
    const float* qw   = (const float*)d_in[7];
    const float* kw   = (const float*)d_in[8];
    float* out = (float*)d_out;

    __half *p_hs, *p_wqt, *p_wkvt, *p_wot, *p_attn;
    float *p_qg, *p_kv;
    cudaGetSymbolAddress((void**)&p_hs,   g_hs);
    cudaGetSymbolAddress((void**)&p_wqt,  g_wqt);
    cudaGetSymbolAddress((void**)&p_wkvt, g_wkvt);
    cudaGetSymbolAddress((void**)&p_wot,  g_wot);
    cudaGetSymbolAddress((void**)&p_qg,   g_qg);
    cudaGetSymbolAddress((void**)&p_kv,   g_kv);
    cudaGetSymbolAddress((void**)&p_attn, g_attn);

    // 0) Prep: panelize hs (A) and weights (B)
    pack_hs_kernel<<<1024, 256>>>(hs, p_hs);
    pack_w_kernel<<<dim3(QGN / 32, HID / 32), dim3(32, 8)>>>(Wq, p_wqt, HID, QGN, 32, 0);
    pack_w_kernel<<<dim3(KVN / 32, HID / 32), dim3(32, 8)>>>(Wk, p_wkvt, HID, KVN, 32, 0);
    pack_w_kernel<<<dim3(KVN / 32, HID / 32), dim3(32, 8)>>>(Wv, p_wkvt, HID, KVN, 32, KVN);
    pack_w_kernel<<<dim3(HID / 32, ODIM / 32), dim3(32, 8)>>>(Wo, p_wot, ODIM, HID, 64, 0);

    // 1) Projections (bulk-copy pipelined fp16 mma)
    cudaFuncSetAttribute(hgemm_kernel, cudaFuncAttributeMaxDynamicSharedMemorySize, GK_SMEM);
    hgemm_kernel<<<dim3(QGN / 128, MM / 256), 256, GK_SMEM>>>(p_hs, p_wqt, p_qg, QGN, 32);
    hgemm_kernel<<<dim3(2*KVN / 128, MM / 256), 256, GK_SMEM>>>(p_hs, p_wkvt, p_kv, 2*KVN, 32);

    // 2) RMSNorm + RoPE + V transpose (fp16 outputs)
    qkv_post_kernel<<<dim3(MM, 20), 256>>>(cosp, sinp, qw, kw);

    // 3) Flash attention + gate
    cudaFuncSetAttribute(flash_kernel, cudaFuncAttributeMaxDynamicSharedMemorySize, FL_SMEM);
    flash_kernel<<<dim3(SS / 128, BB * NH), 256, FL_SMEM>>>();

    // 4) Output projection
    hgemm_kernel<<<dim3(HID / 128, MM / 256), 256, GK_SMEM>>>(p_attn, p_wot, out, HID, 64);
}

// round 9
// speedup vs baseline: 1.2050x; 1.2050x over previous
#include <cuda_runtime.h>
#include <cuda_fp16.h>
#include <math.h>

// Problem constants
#define BB 2
#define SS 2048
#define HID 2048
#define NH 16
#define NKVH 2
#define DH 256
#define ROT 64
#define MM (BB*SS)          // 4096 tokens
#define QGN (NH*DH*2)       // 8192
#define KVN (NKVH*DH)       // 512
#define ODIM (NH*DH)        // 4096

// Scratch (device globals)
__device__ __half g_hs  [(size_t)MM * HID];          // fp16 hidden states
__device__ __half g_wqt [(size_t)QGN * HID];         // Wq^T  [N][K] fp16
__device__ __half g_wkvt[(size_t)(2*KVN) * HID];     // [Wk^T; Wv^T] fp16
__device__ __half g_wot [(size_t)HID * ODIM];        // Wo^T fp16
__device__ float  g_qg  [(size_t)MM * QGN];          // [token][h*512 + (q|gate)] fp32
__device__ float  g_kv  [(size_t)MM * 2*KVN];        // [token][k | v] fp32
__device__ __half g_q   [(size_t)BB * NH  * SS * DH];   // [b][h][s][d], scale folded
__device__ __half g_kr  [(size_t)BB * NKVH * SS * DH];  // [b][kvh][s][d]
__device__ __half g_vr  [(size_t)BB * NKVH * DH * SS];  // [b][kvh][d][s] (TRANSPOSED)
__device__ __half g_attn[(size_t)MM * ODIM];            // fp16 attn output

// ---------------- device helpers ----------------
__device__ __forceinline__ unsigned smem_u32(const void* p) {
    unsigned a;
    asm("{ .reg .u64 t; cvta.to.shared.u64 t, %1; cvt.u32.u64 %0, t; }" : "=r"(a) : "l"(p));
    return a;
}
__device__ __forceinline__ void mma_f16(float c[4], const unsigned a[4], const unsigned* b) {
    asm volatile(
        "mma.sync.aligned.m16n8k16.row.col.f32.f16.f16.f32 "
        "{%0,%1,%2,%3}, {%4,%5,%6,%7}, {%8,%9}, {%0,%1,%2,%3};\n"
        : "+f"(c[0]), "+f"(c[1]), "+f"(c[2]), "+f"(c[3])
        : "r"(a[0]), "r"(a[1]), "r"(a[2]), "r"(a[3]), "r"(b[0]), "r"(b[1]));
}
__device__ __forceinline__ void ldsm4(unsigned r[4], const __half* p) {
    unsigned a = smem_u32(p);
    asm volatile("ldmatrix.sync.aligned.m8n8.x4.shared.b16 {%0,%1,%2,%3}, [%4];\n"
                 : "=r"(r[0]), "=r"(r[1]), "=r"(r[2]), "=r"(r[3]) : "r"(a));
}
__device__ __forceinline__ void cp16(void* dst, const void* src) {
    unsigned d = (unsigned)__cvta_generic_to_shared(dst);
    asm volatile("cp.async.cg.shared.global [%0], [%1], 16;\n" :: "r"(d), "l"(src));
}
__device__ __forceinline__ void cp_commit() { asm volatile("cp.async.commit_group;\n"); }

// ---------------------------------------------------------------------------
// Prep: fp32 -> fp16
// ---------------------------------------------------------------------------
__global__ __launch_bounds__(256) void half_kernel(const float* __restrict__ src,
                                                   __half* __restrict__ dst, int n8)
{
    for (int i = blockIdx.x * 256 + threadIdx.x; i < n8; i += gridDim.x * 256) {
        float4 v0 = ((const float4*)src)[i * 2];
        float4 v1 = ((const float4*)src)[i * 2 + 1];
        __half2 h[4];
        h[0] = __floats2half2_rn(v0.x, v0.y);
        h[1] = __floats2half2_rn(v0.z, v0.w);
        h[2] = __floats2half2_rn(v1.x, v1.y);
        h[3] = __floats2half2_rn(v1.z, v1.w);
        ((uint4*)dst)[i] = *(uint4*)h;
    }
}

// ---------------------------------------------------------------------------
// Prep: transpose + fp16. src [R][C] fp32 -> dst [C][R] fp16.
// ---------------------------------------------------------------------------
__global__ __launch_bounds__(256) void transpose_half_kernel(
    const float* __restrict__ src, __half* __restrict__ dst, int R, int C)
{
    __shared__ float t[32][33];
    const int x = blockIdx.x * 32 + threadIdx.x;
    const int y0 = blockIdx.y * 32;
#pragma unroll
    for (int i = 0; i < 32; i += 8)
        t[threadIdx.y + i][threadIdx.x] = src[(size_t)(y0 + threadIdx.y + i) * C + x];
    __syncthreads();
    const int nx = blockIdx.y * 32 + threadIdx.x;
    const int ny0 = blockIdx.x * 32;
#pragma unroll
    for (int i = 0; i < 32; i += 8)
        dst[(size_t)(ny0 + threadIdx.y + i) * R + nx] =
            __float2half(t[threadIdx.x][threadIdx.y + i]);
}

// ---------------------------------------------------------------------------
// fp16 GEMM: A [M][K] fp16, Bt [N][K] fp16, C [M][N] fp32.
// CTA tile 256x128, BK=32, THREE-stage cp.async ring, 8 warps (4x2),
// warp tile 64x64.
// ---------------------------------------------------------------------------
#define GS_STR 40   // halfs; 80B row stride -> conflict-free ldmatrix
#define TG_SMEM ((3*256*GS_STR + 3*128*GS_STR) * (int)sizeof(__half))

__global__ __launch_bounds__(256, 1) void hgemm_kernel(
    const __half* __restrict__ A, const __half* __restrict__ Bt,
    float* __restrict__ C, int M, int N, int K)
{
    extern __shared__ __half hsm[];
    __half* As = hsm;                        // [3][256][GS_STR]
    __half* Bs = hsm + 3 * 256 * GS_STR;     // [3][128][GS_STR]

    const int tid = threadIdx.x;
    const int bx = blockIdx.x, by = blockIdx.y;
    const int lane = tid & 31;
    const int g = lane >> 2, t = lane & 3;
    const int wid = tid >> 5;
    const int m0 = (wid >> 1) * 64;
    const int n0 = (wid & 1) * 64;

    const int a_row = ((lane >> 3) & 1) * 8 + (lane & 7);
    const int a_kh  = (lane >> 4) * 8;
    const int b_row = ((lane >> 4) & 1) * 8 + (lane & 7);
    const int b_kh  = ((lane >> 3) & 1) * 8;

    const int nk = K >> 5;

    auto issue = [&](int st, int k0) {
        __half* Ad = As + (size_t)st * 256 * GS_STR;
        __half* Bd = Bs + (size_t)st * 128 * GS_STR;
#pragma unroll
        for (int it = 0; it < 4; it++) {
            int idx = tid + it * 256;
            int row = idx >> 2;
            int ch  = (idx & 3) * 8;
            cp16(Ad + row * GS_STR + ch, A + (size_t)(by * 256 + row) * K + k0 + ch);
        }
#pragma unroll
        for (int it = 0; it < 2; it++) {
            int idx = tid + it * 256;
            int row = idx >> 2;
            int ch  = (idx & 3) * 8;
            cp16(Bd + row * GS_STR + ch, Bt + (size_t)(bx * 128 + row) * K + k0 + ch);
        }
        cp_commit();
    };

    issue(0, 0);
    if (nk > 1) issue(1, 32);
    if (nk > 2) issue(2, 64);

    float acc[4][8][4];
#pragma unroll
    for (int mt = 0; mt < 4; mt++)
#pragma unroll
        for (int nt = 0; nt < 8; nt++)
#pragma unroll
            for (int r = 0; r < 4; r++) acc[mt][nt][r] = 0.f;

    for (int i = 0; i < nk; i++) {
        const int st = i % 3;
        __half* Ad = As + (size_t)st * 256 * GS_STR;
        __half* Bd = Bs + (size_t)st * 128 * GS_STR;
        if (i + 2 < nk)      asm volatile("cp.async.wait_group 2;\n");
        else if (i + 1 < nk) asm volatile("cp.async.wait_group 1;\n");
        else                 asm volatile("cp.async.wait_group 0;\n");
        __syncthreads();

#pragma unroll
        for (int kk = 0; kk < 32; kk += 16) {
            unsigned a[4][4], bfr[4][4];
#pragma unroll
            for (int mt = 0; mt < 4; mt++)
                ldsm4(a[mt], Ad + (m0 + mt * 16 + a_row) * GS_STR + kk + a_kh);
#pragma unroll
            for (int p = 0; p < 4; p++)
                ldsm4(bfr[p], Bd + (n0 + p * 16 + b_row) * GS_STR + kk + b_kh);
#pragma unroll
            for (int mt = 0; mt < 4; mt++)
#pragma unroll
                for (int nt = 0; nt < 8; nt++)
                    mma_f16(acc[mt][nt], a[mt], &bfr[nt >> 1][(nt & 1) * 2]);
        }
        __syncthreads();
        if (i + 3 < nk) issue(st, (i + 3) * 32);
    }

#pragma unroll
    for (int mt = 0; mt < 4; mt++) {
        const int r = by * 256 + m0 + mt * 16 + g;
#pragma unroll
        for (int nt = 0; nt < 8; nt++) {
            const int c = bx * 128 + n0 + nt * 8 + 2 * t;
            *(float2*)(C + (size_t)r * N + c)       = make_float2(acc[mt][nt][0], acc[mt][nt][1]);
            *(float2*)(C + (size_t)(r + 8) * N + c) = make_float2(acc[mt][nt][2], acc[mt][nt][3]);
        }
    }
}

// ---------------------------------------------------------------------------
// Post-process: RMSNorm + RoPE for Q/K, V transpose. fp16 outputs, scale folded.
// ---------------------------------------------------------------------------
__global__ __launch_bounds__(256) void qkv_post_kernel(
    const float* __restrict__ cosp, const float* __restrict__ sinp,
    const float* __restrict__ qw, const float* __restrict__ kw)
{
    const int token = blockIdx.x;
    const int unit  = blockIdx.y;
    const int d     = threadIdx.x;
    const int b = token >> 11;
    const int s = token & 2047;

    __shared__ float sh[DH];
    __shared__ float red[8];

    if (unit < 18) {
        float x;
        const float* w;
        if (unit < 16) {
            x = g_qg[(size_t)token * QGN + unit * 512 + d];
            w = qw;
        } else {
            x = g_kv[(size_t)token * (2*KVN) + (unit - 16) * 256 + d];
            w = kw;
        }
        float v = x * x;
#pragma unroll
        for (int o = 16; o; o >>= 1) v += __shfl_xor_sync(0xffffffffu, v, o);
        if ((d & 31) == 0) red[d >> 5] = v;
        __syncthreads();
        float tot = 0.f;
#pragma unroll
        for (int i = 0; i < 8; i++) tot += red[i];
        float xn = x * rsqrtf(tot * (1.0f / 256.0f) + 1e-6f) * (1.0f + w[d]);
        sh[d] = xn;
        __syncthreads();
        float out = xn;
        if (d < ROT) {
            float rot = (d < 32) ? -sh[d + 32] : sh[d - 32];
            out = xn * cosp[(size_t)token * ROT + d] + rot * sinp[(size_t)token * ROT + d];
        }
        if (unit < 16)
            g_q[(((size_t)b * NH + unit) * SS + s) * DH + d] = __float2half(out * 0.0625f);
        else
            g_kr[(((size_t)b * NKVH + (unit - 16)) * SS + s) * DH + d] = __float2half(out);
    } else {
        const int kvh = unit - 18;
        g_vr[(((size_t)b * NKVH + kvh) * DH + d) * SS + s] =
            __float2half(g_kv[(size_t)token * (2*KVN) + 512 + kvh * 256 + d]);
    }
}

// ---------------------------------------------------------------------------
// Flash attention (fp16 mma m16n8k16 + ldmatrix). q-tile 128 (Q resident),
// key-tile 64, K double-buffered via cp.async, V pipelined (single buffer,
// wait deferred to just before PV). Heavy q-tiles scheduled first.
// ---------------------------------------------------------------------------
#define QS_STR 264
#define KS_STR 264
#define VS_STR 72
#define PS_STR 72
#define FL_SMEM ((128*QS_STR + 2*64*KS_STR + 256*VS_STR + 128*PS_STR) * 2 + 512 * 4)

__global__ __launch_bounds__(256, 1) void flash_kernel()
{
    extern __shared__ __half smh[];
    __half* Qs = smh;                        // [128][QS_STR]
    __half* Ks = Qs + 128 * QS_STR;          // [2][64][KS_STR] (full D=256)
    __half* Vs = Ks + 2 * 64 * KS_STR;       // [256][VS_STR]   ([d][key])
    __half* Ps = Vs + 256 * VS_STR;          // [128][PS_STR]
    float* redm = (float*)(Ps + 128 * PS_STR);   // [2][128]
    float* redl = redm + 256;                    // [2][128]

    const int tid = threadIdx.x;
    const int lane = tid & 31;
    const int g = lane >> 2, t = lane & 3;
    const int wid = tid >> 5;
    const int wm = wid >> 1;
    const int wn = wid & 1;

    const int a_row = ((lane >> 3) & 1) * 8 + (lane & 7);
    const int a_kh  = (lane >> 4) * 8;
    const int b_row = ((lane >> 4) & 1) * 8 + (lane & 7);
    const int b_kh  = ((lane >> 3) & 1) * 8;

    const int qt = (int)gridDim.x - 1 - (int)blockIdx.x;   // heavy tiles first
    const int b  = blockIdx.y >> 4;
    const int h  = blockIdx.y & 15;
    const int kvh = h >> 3;
    const int q0 = qt * 128;

    const __half* Qp  = g_q  + (((size_t)b * NH + h) * SS + q0) * DH;
    const __half* Kp  = g_kr + ((size_t)b * NKVH + kvh) * SS * DH;
    const __half* VpT = g_vr + ((size_t)b * NKVH + kvh) * DH * SS;

    // K tile loader: stage s, tile kt (8 cp16 per thread)
    auto issueK = [&](int kt, int s) {
        const __half* Kt = Kp + (size_t)(kt * 64) * DH;
        __half* Kd = Ks + s * 64 * KS_STR;
#pragma unroll
        for (int it = 0; it < 8; it++) {
            const int idx = tid + it * 256;
            const int key = idx >> 5;
            const int col = (idx & 31) * 8;
            cp16(Kd + key * KS_STR + col, Kt + (size_t)key * DH + col);
        }
    };
    // V tile loader (8 cp16 per thread)
    auto issueV = [&](int kt) {
#pragma unroll
        for (int it = 0; it < 8; it++) {
            const int idx = tid + it * 256;
            const int dl = idx >> 3;
            const int kc = (idx & 7) * 8;
            cp16(Vs + dl * VS_STR + kc, VpT + (size_t)dl * SS + kt * 64 + kc);
        }
    };

    // Load Q block (resident): 128 rows x 256 halfs
#pragma unroll
    for (int it = 0; it < 16; it++) {
        const int idx = tid + it * 256;
        const int r = idx >> 5;
        const int c = (idx & 31) * 8;
        *(uint4*)&Qs[r * QS_STR + c] = *(const uint4*)(Qp + (size_t)r * DH + c);
    }

    float o[2][16][4];
    float mrun[4], lrun[4];
#pragma unroll
    for (int mt = 0; mt < 2; mt++)
#pragma unroll
        for (int cc = 0; cc < 16; cc++)
#pragma unroll
            for (int r = 0; r < 4; r++) o[mt][cc][r] = 0.f;
#pragma unroll
    for (int i = 0; i < 4; i++) { mrun[i] = -1e30f; lrun[i] = 0.f; }

    const int ktmax = 2 * qt + 1;

    // prologue: K(0) in flight
    issueK(0, 0);
    cp_commit();

    for (int kt = 0; kt <= ktmax; kt++) {
        // top barrier: all threads done with PV(kt-1) (Vs) and QK(kt-1) (Ks stage)
        __syncthreads();
        if (kt + 1 <= ktmax) issueK(kt + 1, (kt + 1) & 1);
        issueV(kt);
        cp_commit();

        // K(kt) ready (allow the just-committed group to stay pending)
        asm volatile("cp.async.wait_group 1;\n");
        __syncthreads();

        const __half* Kd = Ks + (kt & 1) * 64 * KS_STR;

        float s[2][4][4];
#pragma unroll
        for (int mt = 0; mt < 2; mt++)
#pragma unroll
            for (int nt = 0; nt < 4; nt++)
#pragma unroll
                for (int r = 0; r < 4; r++) s[mt][nt][r] = 0.f;

#pragma unroll
        for (int kk = 0; kk < 256; kk += 16) {
            unsigned a[2][4], bq[2][4];
            ldsm4(a[0], Qs + (wm * 32 + a_row)      * QS_STR + kk + a_kh);
            ldsm4(a[1], Qs + (wm * 32 + 16 + a_row) * QS_STR + kk + a_kh);
            ldsm4(bq[0], Kd + (wn * 32 + b_row)      * KS_STR + kk + b_kh);
            ldsm4(bq[1], Kd + (wn * 32 + 16 + b_row) * KS_STR + kk + b_kh);
#pragma unroll
            for (int mt = 0; mt < 2; mt++)
#pragma unroll
                for (int nt = 0; nt < 4; nt++)
                    mma_f16(s[mt][nt], a[mt], &bq[nt >> 1][(nt & 1) * 2]);
        }

        if (kt >= 2 * qt) {
#pragma unroll
            for (int mt = 0; mt < 2; mt++)
#pragma unroll
                for (int nt = 0; nt < 4; nt++)
#pragma unroll
                    for (int r = 0; r < 4; r++) {
                        const int row = q0 + wm * 32 + mt * 16 + (r >> 1) * 8 + g;
                        const int col = kt * 64 + wn * 32 + nt * 8 + 2 * t + (r & 1);
                        if (col > row) s[mt][nt][r] = -1e30f;
                    }
        }

        float al[4];
#pragma unroll
        for (int mt = 0; mt < 2; mt++)
#pragma unroll
            for (int hh = 0; hh < 2; hh++) {
                float v = -1e30f;
#pragma unroll
                for (int nt = 0; nt < 4; nt++)
                    v = fmaxf(v, fmaxf(s[mt][nt][hh * 2], s[mt][nt][hh * 2 + 1]));
                v = fmaxf(v, __shfl_xor_sync(0xffffffffu, v, 1));
                v = fmaxf(v, __shfl_xor_sync(0xffffffffu, v, 2));
                if (t == 0) redm[wn * 128 + wm * 32 + mt * 16 + hh * 8 + g] = v;
            }
        __syncthreads();
#pragma unroll
        for (int mt = 0; mt < 2; mt++)
#pragma unroll
            for (int hh = 0; hh < 2; hh++) {
                const int idx = mt * 2 + hh;
                const int rl = wm * 32 + mt * 16 + hh * 8 + g;
                float tm = fmaxf(redm[rl], redm[128 + rl]);
                float mn = fmaxf(mrun[idx], tm);
                al[idx] = __expf(mrun[idx] - mn);
                mrun[idx] = mn;
                float rs = 0.f;
#pragma unroll
                for (int nt = 0; nt < 4; nt++)
#pragma unroll
                    for (int j = 0; j < 2; j++) {
                        float p = __expf(s[mt][nt][hh * 2 + j] - mn);
                        s[mt][nt][hh * 2 + j] = p;
                        rs += p;
                    }
                rs += __shfl_xor_sync(0xffffffffu, rs, 1);
                rs += __shfl_xor_sync(0xffffffffu, rs, 2);
                if (t == 0) redl[wn * 128 + rl] = rs;
            }
#pragma unroll
        for (int mt = 0; mt < 2; mt++)
#pragma unroll
            for (int nt = 0; nt < 4; nt++) {
                const int r = wm * 32 + mt * 16 + g;
                const int c = wn * 32 + nt * 8 + 2 * t;
                *(__half2*)&Ps[r * PS_STR + c] =
                    __floats2half2_rn(s[mt][nt][0], s[mt][nt][1]);
                *(__half2*)&Ps[(r + 8) * PS_STR + c] =
                    __floats2half2_rn(s[mt][nt][2], s[mt][nt][3]);
            }
        // V(kt) (and K(kt+1)) must have landed before PV reads Vs
        asm volatile("cp.async.wait_group 0;\n");
        __syncthreads();
#pragma unroll
        for (int mt = 0; mt < 2; mt++)
#pragma unroll
            for (int hh = 0; hh < 2; hh++) {
                const int idx = mt * 2 + hh;
                const int rl = wm * 32 + mt * 16 + hh * 8 + g;
                float ts = redl[rl] + redl[128 + rl];
                lrun[idx] = lrun[idx] * al[idx] + ts;
#pragma unroll
                for (int cc = 0; cc < 16; cc++) {
                    o[mt][cc][hh * 2]     *= al[idx];
                    o[mt][cc][hh * 2 + 1] *= al[idx];
                }
            }

#pragma unroll
        for (int kk = 0; kk < 64; kk += 16) {
            unsigned a[2][4], bv[8][4];
            ldsm4(a[0], Ps + (wm * 32 + a_row)      * PS_STR + kk + a_kh);
            ldsm4(a[1], Ps + (wm * 32 + 16 + a_row) * PS_STR + kk + a_kh);
#pragma unroll
            for (int p = 0; p < 8; p++)
                ldsm4(bv[p], Vs + (wn * 128 + p * 16 + b_row) * VS_STR + kk + b_kh);
#pragma unroll
            for (int mt = 0; mt < 2; mt++)
#pragma unroll
                for (int nt = 0; nt < 16; nt++)
                    mma_f16(o[mt][nt], a[mt], &bv[nt >> 1][(nt & 1) * 2]);
        }
    }

#pragma unroll
    for (int mt = 0; mt < 2; mt++)
#pragma unroll
        for (int hh = 0; hh < 2; hh++) {
            const int idx = mt * 2 + hh;
            const int row = q0 + wm * 32 + mt * 16 + hh * 8 + g;
            const size_t token = (size_t)b * SS + row;
            const float inv = 1.f / lrun[idx];
#pragma unroll
            for (int cc = 0; cc < 16; cc++) {
                const int col = wn * 128 + cc * 8 + 2 * t;
                float2 gt = *(const float2*)(g_qg + token * QGN + h * 512 + 256 + col);
                float ox = o[mt][cc][hh * 2]     * inv / (1.f + __expf(-gt.x));
                float oy = o[mt][cc][hh * 2 + 1] * inv / (1.f + __expf(-gt.y));
                *(__half2*)(g_attn + token * ODIM + h * 256 + col) =
                    __floats2half2_rn(ox, oy);
            }
        }
}

// ---------------------------------------------------------------------------
extern "C" void kernel_launch(void* const* d_in, const int* in_sizes, int n_in,
                              void* d_out, int out_size)
{
    (void)in_sizes; (void)n_in; (void)out_size;
    const float* hs   = (const float*)d_in[0];
    const float* cosp = (const float*)d_in[1];
    const float* sinp = (const float*)d_in[2];
    const float* Wq   = (const float*)d_in[3];
    const float* Wk   = (const float*)d_in[4];
    const float* Wv   = (const float*)d_in[5];
    const float* Wo   = (const float*)d_in[6];
    const float* qw   = (const float*)d_in[7];
    const float* kw   = (const float*)d_in[8];
    float* out = (float*)d_out;

    __half *p_hs, *p_wqt, *p_wkvt, *p_wot, *p_attn;
    float *p_qg, *p_kv;
    cudaGetSymbolAddress((void**)&p_hs,   g_hs);
    cudaGetSymbolAddress((void**)&p_wqt,  g_wqt);
    cudaGetSymbolAddress((void**)&p_wkvt, g_wkvt);
    cudaGetSymbolAddress((void**)&p_wot,  g_wot);
    cudaGetSymbolAddress((void**)&p_qg,   g_qg);
    cudaGetSymbolAddress((void**)&p_kv,   g_kv);
    cudaGetSymbolAddress((void**)&p_attn, g_attn);

    // 0) Prep: fp16 hs; transpose+fp16 weights
    half_kernel<<<1024, 256>>>(hs, p_hs, MM * HID / 8);
    transpose_half_kernel<<<dim3(QGN / 32, HID / 32), dim3(32, 8)>>>(Wq, p_wqt, HID, QGN);
    transpose_half_kernel<<<dim3(KVN / 32, HID / 32), dim3(32, 8)>>>(Wk, p_wkvt, HID, KVN);
    transpose_half_kernel<<<dim3(KVN / 32, HID / 32), dim3(32, 8)>>>(Wv, p_wkvt + (size_t)KVN * HID, HID, KVN);
    transpose_half_kernel<<<dim3(HID / 32, ODIM / 32), dim3(32, 8)>>>(Wo, p_wot, ODIM, HID);

    // 1) Projections (fp16 mma, 3-stage cp.async)
    cudaFuncSetAttribute(hgemm_kernel, cudaFuncAttributeMaxDynamicSharedMemorySize, TG_SMEM);
    hgemm_kernel<<<dim3(QGN / 128, MM / 256), 256, TG_SMEM>>>(p_hs, p_wqt, p_qg, MM, QGN, HID);
    hgemm_kernel<<<dim3(2*KVN / 128, MM / 256), 256, TG_SMEM>>>(p_hs, p_wkvt, p_kv, MM, 2*KVN, HID);

    // 2) RMSNorm + RoPE + V transpose (fp16 outputs)
    qkv_post_kernel<<<dim3(MM, 20), 256>>>(cosp, sinp, qw, kw);

    // 3) Flash attention + gate (pipelined K/V)
    cudaFuncSetAttribute(flash_kernel, cudaFuncAttributeMaxDynamicSharedMemorySize, FL_SMEM);
    flash_kernel<<<dim3(SS / 128, BB * NH), 256, FL_SMEM>>>();

    // 4) Output projection
    hgemm_kernel<<<dim3(HID / 128, MM / 256), 256, TG_SMEM>>>(p_attn, p_wot, out, MM, HID, ODIM);
}

// round 10
// speedup vs baseline: 1.2479x; 1.0355x over previous
#include <cuda_runtime.h>
#include <cuda_fp16.h>
#include <math.h>

// Problem constants
#define BB 2
#define SS 2048
#define HID 2048
#define NH 16
#define NKVH 2
#define DH 256
#define ROT 64
#define MM (BB*SS)          // 4096 tokens
#define QGN (NH*DH*2)       // 8192
#define KVN (NKVH*DH)       // 512
#define ODIM (NH*DH)        // 4096

// Scratch (device globals)
__device__ __half g_hs  [(size_t)MM * HID];
__device__ __half g_wqt [(size_t)QGN * HID];
__device__ __half g_wkvt[(size_t)(2*KVN) * HID];
__device__ __half g_wot [(size_t)HID * ODIM];
__device__ float  g_qg  [(size_t)MM * QGN];
__device__ float  g_kv  [(size_t)MM * 2*KVN];
__device__ __half g_q   [(size_t)BB * NH  * SS * DH];
__device__ __half g_kr  [(size_t)BB * NKVH * SS * DH];
__device__ __half g_vr  [(size_t)BB * NKVH * DH * SS];   // [b][kvh][d][s]
__device__ __half g_attn[(size_t)MM * ODIM];

// ---------------- device helpers ----------------
__device__ __forceinline__ unsigned smem_u32(const void* p) {
    unsigned a;
    asm("{ .reg .u64 t; cvta.to.shared.u64 t, %1; cvt.u32.u64 %0, t; }" : "=r"(a) : "l"(p));
    return a;
}
__device__ __forceinline__ void mma_f16(float c[4], const unsigned a[4], const unsigned* b) {
    asm volatile(
        "mma.sync.aligned.m16n8k16.row.col.f32.f16.f16.f32 "
        "{%0,%1,%2,%3}, {%4,%5,%6,%7}, {%8,%9}, {%0,%1,%2,%3};\n"
        : "+f"(c[0]), "+f"(c[1]), "+f"(c[2]), "+f"(c[3])
        : "r"(a[0]), "r"(a[1]), "r"(a[2]), "r"(a[3]), "r"(b[0]), "r"(b[1]));
}
__device__ __forceinline__ void ldsm4(unsigned r[4], const __half* p) {
    unsigned a = smem_u32(p);
    asm volatile("ldmatrix.sync.aligned.m8n8.x4.shared.b16 {%0,%1,%2,%3}, [%4];\n"
                 : "=r"(r[0]), "=r"(r[1]), "=r"(r[2]), "=r"(r[3]) : "r"(a));
}
__device__ __forceinline__ void cp16(void* dst, const void* src) {
    unsigned d = (unsigned)__cvta_generic_to_shared(dst);
    asm volatile("cp.async.cg.shared.global [%0], [%1], 16;\n" :: "r"(d), "l"(src));
}
__device__ __forceinline__ void cp_commit() { asm volatile("cp.async.commit_group;\n"); }
__device__ __forceinline__ unsigned pack_h2(float a, float b) {
    __half2 h = __floats2half2_rn(a, b);
    return *(unsigned*)&h;
}

// ---------------------------------------------------------------------------
// Prep: fp32 -> fp16
// ---------------------------------------------------------------------------
__global__ __launch_bounds__(256) void half_kernel(const float* __restrict__ src,
                                                   __half* __restrict__ dst, int n8)
{
    for (int i = blockIdx.x * 256 + threadIdx.x; i < n8; i += gridDim.x * 256) {
        float4 v0 = ((const float4*)src)[i * 2];
        float4 v1 = ((const float4*)src)[i * 2 + 1];
        __half2 h[4];
        h[0] = __floats2half2_rn(v0.x, v0.y);
        h[1] = __floats2half2_rn(v0.z, v0.w);
        h[2] = __floats2half2_rn(v1.x, v1.y);
        h[3] = __floats2half2_rn(v1.z, v1.w);
        ((uint4*)dst)[i] = *(uint4*)h;
    }
}

// ---------------------------------------------------------------------------
// Prep: transpose + fp16. src [R][C] fp32 -> dst [C][R] fp16.
// ---------------------------------------------------------------------------
__global__ __launch_bounds__(256) void transpose_half_kernel(
    const float* __restrict__ src, __half* __restrict__ dst, int R, int C)
{
    __shared__ float t[32][33];
    const int x = blockIdx.x * 32 + threadIdx.x;
    const int y0 = blockIdx.y * 32;
#pragma unroll
    for (int i = 0; i < 32; i += 8)
        t[threadIdx.y + i][threadIdx.x] = src[(size_t)(y0 + threadIdx.y + i) * C + x];
    __syncthreads();
    const int nx = blockIdx.y * 32 + threadIdx.x;
    const int ny0 = blockIdx.x * 32;
#pragma unroll
    for (int i = 0; i < 32; i += 8)
        dst[(size_t)(ny0 + threadIdx.y + i) * R + nx] =
            __float2half(t[threadIdx.x][threadIdx.y + i]);
}

// ---------------------------------------------------------------------------
// fp16 GEMM (3-stage cp.async), DUAL-OUTPUT: blocks bx < nbx1 compute
// C1 = A @ B1t (width N1), the rest compute C2 = A @ B2t (width N2).
// CTA tile 256x128, BK=32, 8 warps (4x2), warp 64x64.
// ---------------------------------------------------------------------------
#define GS_STR 40
#define TG_SMEM ((3*256*GS_STR + 3*128*GS_STR) * (int)sizeof(__half))

__global__ __launch_bounds__(256, 1) void hgemm_kernel(
    const __half* __restrict__ A,
    const __half* __restrict__ B1t, float* __restrict__ C1, int N1,
    const __half* __restrict__ B2t, float* __restrict__ C2, int N2,
    int K, int nbx1)
{
    extern __shared__ __half hsm[];
    __half* As = hsm;
    __half* Bs = hsm + 3 * 256 * GS_STR;

    const int tid = threadIdx.x;
    int bx = blockIdx.x;
    const int by = blockIdx.y;
    const __half* Bt; float* C; int N;
    if (bx < nbx1) { Bt = B1t; C = C1; N = N1; }
    else           { bx -= nbx1; Bt = B2t; C = C2; N = N2; }

    const int lane = tid & 31;
    const int g = lane >> 2, t = lane & 3;
    const int wid = tid >> 5;
    const int m0 = (wid >> 1) * 64;
    const int n0 = (wid & 1) * 64;

    const int a_row = ((lane >> 3) & 1) * 8 + (lane & 7);
    const int a_kh  = (lane >> 4) * 8;
    const int b_row = ((lane >> 4) & 1) * 8 + (lane & 7);
    const int b_kh  = ((lane >> 3) & 1) * 8;

    const int nk = K >> 5;

    auto issue = [&](int st, int k0) {
        __half* Ad = As + (size_t)st * 256 * GS_STR;
        __half* Bd = Bs + (size_t)st * 128 * GS_STR;
#pragma unroll
        for (int it = 0; it < 4; it++) {
            int idx = tid + it * 256;
            int row = idx >> 2;
            int ch  = (idx & 3) * 8;
            cp16(Ad + row * GS_STR + ch, A + (size_t)(by * 256 + row) * K + k0 + ch);
        }
#pragma unroll
        for (int it = 0; it < 2; it++) {
            int idx = tid + it * 256;
            int row = idx >> 2;
            int ch  = (idx & 3) * 8;
            cp16(Bd + row * GS_STR + ch, Bt + (size_t)(bx * 128 + row) * K + k0 + ch);
        }
        cp_commit();
    };

    issue(0, 0);
    if (nk > 1) issue(1, 32);
    if (nk > 2) issue(2, 64);

    float acc[4][8][4];
#pragma unroll
    for (int mt = 0; mt < 4; mt++)
#pragma unroll
        for (int nt = 0; nt < 8; nt++)
#pragma unroll
            for (int r = 0; r < 4; r++) acc[mt][nt][r] = 0.f;

    for (int i = 0; i < nk; i++) {
        const int st = i % 3;
        __half* Ad = As + (size_t)st * 256 * GS_STR;
        __half* Bd = Bs + (size_t)st * 128 * GS_STR;
        if (i + 2 < nk)      asm volatile("cp.async.wait_group 2;\n");
        else if (i + 1 < nk) asm volatile("cp.async.wait_group 1;\n");
        else                 asm volatile("cp.async.wait_group 0;\n");
        __syncthreads();

#pragma unroll
        for (int kk = 0; kk < 32; kk += 16) {
            unsigned a[4][4], bfr[4][4];
#pragma unroll
            for (int mt = 0; mt < 4; mt++)
                ldsm4(a[mt], Ad + (m0 + mt * 16 + a_row) * GS_STR + kk + a_kh);
#pragma unroll
            for (int p = 0; p < 4; p++)
                ldsm4(bfr[p], Bd + (n0 + p * 16 + b_row) * GS_STR + kk + b_kh);
#pragma unroll
            for (int mt = 0; mt < 4; mt++)
#pragma unroll
                for (int nt = 0; nt < 8; nt++)
                    mma_f16(acc[mt][nt], a[mt], &bfr[nt >> 1][(nt & 1) * 2]);
        }
        __syncthreads();
        if (i + 3 < nk) issue(st, (i + 3) * 32);
    }

#pragma unroll
    for (int mt = 0; mt < 4; mt++) {
        const int r = by * 256 + m0 + mt * 16 + g;
#pragma unroll
        for (int nt = 0; nt < 8; nt++) {
            const int c = bx * 128 + n0 + nt * 8 + 2 * t;
            *(float2*)(C + (size_t)r * N + c)       = make_float2(acc[mt][nt][0], acc[mt][nt][1]);
            *(float2*)(C + (size_t)(r + 8) * N + c) = make_float2(acc[mt][nt][2], acc[mt][nt][3]);
        }
    }
}

// ---------------------------------------------------------------------------
// Post-process v2: one WARP per (token, unit). Shfl-only reductions.
// units 0..15: Q rms+rope; 16..17: K rms+rope; 18..19: V transpose.
// grid: 4096*20/8 blocks of 256.
// ---------------------------------------------------------------------------
__global__ __launch_bounds__(256) void qkv_post_kernel(
    const float* __restrict__ cosp, const float* __restrict__ sinp,
    const float* __restrict__ qw, const float* __restrict__ kw)
{
    const int wi = blockIdx.x * 8 + (threadIdx.x >> 5);
    const int lane = threadIdx.x & 31;
    const int token = wi / 20;
    const int unit  = wi % 20;
    const int b = token >> 11;
    const int s = token & 2047;
    const int d0 = lane * 8;

    if (unit >= 18) {
        const int kvh = unit - 18;
        float4 v0 = *(const float4*)(g_kv + (size_t)token * (2*KVN) + 512 + kvh * 256 + d0);
        float4 v1 = *(const float4*)(g_kv + (size_t)token * (2*KVN) + 512 + kvh * 256 + d0 + 4);
        __half* dst = g_vr + (((size_t)b * NKVH + kvh) * DH + d0) * SS + s;
        dst[0 * SS] = __float2half(v0.x); dst[1 * SS] = __float2half(v0.y);
        dst[2 * SS] = __float2half(v0.z); dst[3 * SS] = __float2half(v0.w);
        dst[4 * SS] = __float2half(v1.x); dst[5 * SS] = __float2half(v1.y);
        dst[6 * SS] = __float2half(v1.z); dst[7 * SS] = __float2half(v1.w);
        return;
    }

    const float* src;
    const float* w;
    if (unit < 16) { src = g_qg + (size_t)token * QGN + unit * 512 + d0; w = qw + d0; }
    else           { src = g_kv + (size_t)token * (2*KVN) + (unit - 16) * 256 + d0; w = kw + d0; }

    float x[8];
    *(float4*)(x)     = *(const float4*)(src);
    *(float4*)(x + 4) = *(const float4*)(src + 4);

    float ss = 0.f;
#pragma unroll
    for (int j = 0; j < 8; j++) ss += x[j] * x[j];
#pragma unroll
    for (int o = 16; o; o >>= 1) ss += __shfl_xor_sync(0xffffffffu, ss, o);
    const float rsn = rsqrtf(ss * (1.0f / 256.0f) + 1e-6f);

    float xn[8];
#pragma unroll
    for (int j = 0; j < 8; j++) xn[j] = x[j] * rsn * (1.0f + w[j]);

    // RoPE on d < 64 (lanes 0..7); partner value lives 4 lanes away.
    float rot[8];
#pragma unroll
    for (int j = 0; j < 8; j++) rot[j] = __shfl_xor_sync(0xffffffffu, xn[j], 4);
    if (lane < 8) {
        float cs[8], sn[8];
        *(float4*)(cs)     = *(const float4*)(cosp + (size_t)token * ROT + d0);
        *(float4*)(cs + 4) = *(const float4*)(cosp + (size_t)token * ROT + d0 + 4);
        *(float4*)(sn)     = *(const float4*)(sinp + (size_t)token * ROT + d0);
        *(float4*)(sn + 4) = *(const float4*)(sinp + (size_t)token * ROT + d0 + 4);
#pragma unroll
        for (int j = 0; j < 8; j++) {
            float rr = (lane & 4) ? rot[j] : -rot[j];
            xn[j] = xn[j] * cs[j] + rr * sn[j];
        }
    }

    __half2 h[4];
    if (unit < 16) {
#pragma unroll
        for (int j = 0; j < 4; j++)
            h[j] = __floats2half2_rn(xn[2*j] * 0.0625f, xn[2*j+1] * 0.0625f);
        *(uint4*)(g_q + (((size_t)b * NH + unit) * SS + s) * DH + d0) = *(uint4*)h;
    } else {
#pragma unroll
        for (int j = 0; j < 4; j++)
            h[j] = __floats2half2_rn(xn[2*j], xn[2*j+1]);
        *(uint4*)(g_kr + (((size_t)b * NKVH + (unit - 16)) * SS + s) * DH + d0) = *(uint4*)h;
    }
}

// ---------------------------------------------------------------------------
// Flash attention v6: warp-autonomous. 8 warps x 16 q-rows = 128-row q-tile,
// 64-key tiles, full 64 keys per warp -> shfl-only softmax, P stays in
// registers (QK C-frag == PV A-frag layout). K double-buffered cp.async,
// V single-buffer with deferred wait. Heavy q-tiles first.
// ---------------------------------------------------------------------------
#define QS_STR 264
#define KS_STR 264
#define VS_STR 72
#define FL_SMEM ((128*QS_STR + 2*64*KS_STR + 256*VS_STR) * 2)

__global__ __launch_bounds__(256, 1) void flash_kernel()
{
    extern __shared__ __half smh[];
    __half* Qs = smh;                        // [128][QS_STR]
    __half* Ks = Qs + 128 * QS_STR;          // [2][64][KS_STR]
    __half* Vs = Ks + 2 * 64 * KS_STR;       // [256][VS_STR] ([d][key])

    const int tid = threadIdx.x;
    const int lane = tid & 31;
    const int g = lane >> 2, t = lane & 3;
    const int w = tid >> 5;                  // warp 0..7, rows w*16..+15
    const int rb = w * 16;

    const int a_row = ((lane >> 3) & 1) * 8 + (lane & 7);
    const int a_kh  = (lane >> 4) * 8;
    const int b_row = ((lane >> 4) & 1) * 8 + (lane & 7);
    const int b_kh  = ((lane >> 3) & 1) * 8;

    const int qt = (int)gridDim.x - 1 - (int)blockIdx.x;
    const int b  = blockIdx.y >> 4;
    const int h  = blockIdx.y & 15;
    const int kvh = h >> 3;
    const int q0 = qt * 128;

    const __half* Qp  = g_q  + (((size_t)b * NH + h) * SS + q0) * DH;
    const __half* Kp  = g_kr + ((size_t)b * NKVH + kvh) * SS * DH;
    const __half* VpT = g_vr + ((size_t)b * NKVH + kvh) * DH * SS;

    auto issueK = [&](int kt, int st) {
        const __half* Kt = Kp + (size_t)(kt * 64) * DH;
        __half* Kd = Ks + st * 64 * KS_STR;
#pragma unroll
        for (int it = 0; it < 8; it++) {
            const int idx = tid + it * 256;
            const int key = idx >> 5;
            const int col = (idx & 31) * 8;
            cp16(Kd + key * KS_STR + col, Kt + (size_t)key * DH + col);
        }
    };
    auto issueV = [&](int kt) {
#pragma unroll
        for (int it = 0; it < 8; it++) {
            const int idx = tid + it * 256;
            const int dl = idx >> 3;
            const int kc = (idx & 7) * 8;
            cp16(Vs + dl * VS_STR + kc, VpT + (size_t)dl * SS + kt * 64 + kc);
        }
    };

    // Q resident
#pragma unroll
    for (int it = 0; it < 16; it++) {
        const int idx = tid + it * 256;
        const int r = idx >> 5;
        const int c = (idx & 31) * 8;
        *(uint4*)&Qs[r * QS_STR + c] = *(const uint4*)(Qp + (size_t)r * DH + c);
    }

    float o[32][4];
    float m[2], l[2];
#pragma unroll
    for (int cc = 0; cc < 32; cc++)
#pragma unroll
        for (int r = 0; r < 4; r++) o[cc][r] = 0.f;
    m[0] = m[1] = -1e30f; l[0] = l[1] = 0.f;

    const int ktmax = 2 * qt + 1;

    issueK(0, 0);
    cp_commit();

    for (int kt = 0; kt <= ktmax; kt++) {
        __syncthreads();                     // prev PV done with Vs / Ks stage
        if (kt + 1 <= ktmax) issueK(kt + 1, (kt + 1) & 1);
        issueV(kt);
        cp_commit();

        asm volatile("cp.async.wait_group 1;\n");   // K(kt) landed
        __syncthreads();

        const __half* Kd = Ks + (kt & 1) * 64 * KS_STR;

        float s[8][4];
#pragma unroll
        for (int nt = 0; nt < 8; nt++)
#pragma unroll
            for (int r = 0; r < 4; r++) s[nt][r] = 0.f;

        // ---- S = Q K^T, full 64 keys per warp ----
#pragma unroll
        for (int kk = 0; kk < 256; kk += 16) {
            unsigned a[4], bq[4][4];
            ldsm4(a, Qs + (rb + a_row) * QS_STR + kk + a_kh);
#pragma unroll
            for (int p = 0; p < 4; p++)
                ldsm4(bq[p], Kd + (p * 16 + b_row) * KS_STR + kk + b_kh);
#pragma unroll
            for (int nt = 0; nt < 8; nt++)
                mma_f16(s[nt], a, &bq[nt >> 1][(nt & 1) * 2]);
        }

        // ---- causal mask ----
        if (kt >= 2 * qt) {
#pragma unroll
            for (int nt = 0; nt < 8; nt++)
#pragma unroll
                for (int r = 0; r < 4; r++) {
                    const int row = q0 + rb + (r >> 1) * 8 + g;
                    const int col = kt * 64 + nt * 8 + 2 * t + (r & 1);
                    if (col > row) s[nt][r] = -1e30f;
                }
        }

        // ---- warp-local online softmax (rows span 4 t-lanes) ----
        float al[2];
#pragma unroll
        for (int hh = 0; hh < 2; hh++) {
            float v = -1e30f;
#pragma unroll
            for (int nt = 0; nt < 8; nt++)
                v = fmaxf(v, fmaxf(s[nt][hh * 2], s[nt][hh * 2 + 1]));
            v = fmaxf(v, __shfl_xor_sync(0xffffffffu, v, 1));
            v = fmaxf(v, __shfl_xor_sync(0xffffffffu, v, 2));
            float mn = fmaxf(m[hh], v);
            al[hh] = __expf(m[hh] - mn);
            m[hh] = mn;
            float rs = 0.f;
#pragma unroll
            for (int nt = 0; nt < 8; nt++) {
                float p0 = __expf(s[nt][hh * 2]     - mn);
                float p1 = __expf(s[nt][hh * 2 + 1] - mn);
                s[nt][hh * 2] = p0; s[nt][hh * 2 + 1] = p1;
                rs += p0 + p1;
            }
            rs += __shfl_xor_sync(0xffffffffu, rs, 1);
            rs += __shfl_xor_sync(0xffffffffu, rs, 2);
            l[hh] = l[hh] * al[hh] + rs;
#pragma unroll
            for (int cc = 0; cc < 32; cc++) {
                o[cc][hh * 2]     *= al[hh];
                o[cc][hh * 2 + 1] *= al[hh];
            }
        }

        // V(kt) must have landed before PV reads Vs
        asm volatile("cp.async.wait_group 0;\n");
        __syncthreads();

        // ---- O += P V : P C-frags pack directly into A-frags ----
#pragma unroll
        for (int kk4 = 0; kk4 < 4; kk4++) {
            unsigned pa[4];
            pa[0] = pack_h2(s[2*kk4][0],   s[2*kk4][1]);
            pa[1] = pack_h2(s[2*kk4][2],   s[2*kk4][3]);
            pa[2] = pack_h2(s[2*kk4+1][0], s[2*kk4+1][1]);
            pa[3] = pack_h2(s[2*kk4+1][2], s[2*kk4+1][3]);
#pragma unroll
            for (int half = 0; half < 2; half++) {
                unsigned bv[8][4];
#pragma unroll
                for (int p = 0; p < 8; p++)
                    ldsm4(bv[p], Vs + (half * 128 + p * 16 + b_row) * VS_STR + kk4 * 16 + b_kh);
#pragma unroll
                for (int nt = 0; nt < 16; nt++)
                    mma_f16(o[half * 16 + nt], pa, &bv[nt >> 1][(nt & 1) * 2]);
            }
        }
    }

    // ---- epilogue: /l, * sigmoid(gate) ----
#pragma unroll
    for (int hh = 0; hh < 2; hh++) {
        const int row = q0 + rb + hh * 8 + g;
        const size_t token = (size_t)b * SS + row;
        const float inv = 1.f / l[hh];
#pragma unroll
        for (int cc = 0; cc < 32; cc++) {
            const int col = cc * 8 + 2 * t;
            float2 gt = *(const float2*)(g_qg + token * QGN + h * 512 + 256 + col);
            float ox = o[cc][hh * 2]     * inv / (1.f + __expf(-gt.x));
            float oy = o[cc][hh * 2 + 1] * inv / (1.f + __expf(-gt.y));
            *(__half2*)(g_attn + token * ODIM + h * 256 + col) =
                __floats2half2_rn(ox, oy);
        }
    }
}

// ---------------------------------------------------------------------------
extern "C" void kernel_launch(void* const* d_in, const int* in_sizes, int n_in,
                              void* d_out, int out_size)
{
    (void)in_sizes; (void)n_in; (void)out_size;
    const float* hs   = (const float*)d_in[0];
    const float* cosp = (const float*)d_in[1];
    const float* sinp = (const float*)d_in[2];
    const float* Wq   = (const float*)d_in[3];
    const float* Wk   = (const float*)d_in[4];
    const float* Wv   = (const float*)d_in[5];
    const float* Wo   = (const float*)d_in[6];
    const float* qw   = (const float*)d_in[7];
    const float* kw   = (const float*)d_in[8];
    float* out = (float*)d_out;

    __half *p_hs, *p_wqt, *p_wkvt, *p_wot, *p_attn;
    float *p_qg, *p_kv;
    cudaGetSymbolAddress((void**)&p_hs,   g_hs);
    cudaGetSymbolAddress((void**)&p_wqt,  g_wqt);
    cudaGetSymbolAddress((void**)&p_wkvt, g_wkvt);
    cudaGetSymbolAddress((void**)&p_wot,  g_wot);
    cudaGetSymbolAddress((void**)&p_qg,   g_qg);
    cudaGetSymbolAddress((void**)&p_kv,   g_kv);
    cudaGetSymbolAddress((void**)&p_attn, g_attn);

    // 0) Prep
    half_kernel<<<1024, 256>>>(hs, p_hs, MM * HID / 8);
    transpose_half_kernel<<<dim3(QGN / 32, HID / 32), dim3(32, 8)>>>(Wq, p_wqt, HID, QGN);
    transpose_half_kernel<<<dim3(KVN / 32, HID / 32), dim3(32, 8)>>>(Wk, p_wkvt, HID, KVN);
    transpose_half_kernel<<<dim3(KVN / 32, HID / 32), dim3(32, 8)>>>(Wv, p_wkvt + (size_t)KVN * HID, HID, KVN);
    transpose_half_kernel<<<dim3(HID / 32, ODIM / 32), dim3(32, 8)>>>(Wo, p_wot, ODIM, HID);

    // 1) Fused QG + KV projection (one launch)
    cudaFuncSetAttribute(hgemm_kernel, cudaFuncAttributeMaxDynamicSharedMemorySize, TG_SMEM);
    hgemm_kernel<<<dim3(QGN / 128 + 2*KVN / 128, MM / 256), 256, TG_SMEM>>>(
        p_hs, p_wqt, p_qg, QGN, p_wkvt, p_kv, 2*KVN, HID, QGN / 128);

    // 2) RMSNorm + RoPE + V transpose (warp-per-row)
    qkv_post_kernel<<<MM * 20 / 8, 256>>>(cosp, sinp, qw, kw);

    // 3) Flash attention + gate
    cudaFuncSetAttribute(flash_kernel, cudaFuncAttributeMaxDynamicSharedMemorySize, FL_SMEM);
    flash_kernel<<<dim3(SS / 128, BB * NH), 256, FL_SMEM>>>();

    // 4) Output projection
    hgemm_kernel<<<dim3(HID / 128, MM / 256), 256, TG_SMEM>>>(
        p_attn, p_wot, out, HID, p_wot, out, HID, ODIM, HID / 128);
}